// round 16
// baseline (speedup 1.0000x reference)
#include <cuda_runtime.h>
#include <cuda_fp16.h>

// Problem geometry (fixed by the dataset)
constexpr int Bn = 16;
constexpr int Hh = 352;
constexpr int Ww = 1216;
constexpr int HW = Hh * Ww;           // 428032
constexpr int XQ = Ww / 4;            // 304 x4-positions per row
constexpr int SROWS = 11;             // rows per vertical strip
constexpr int NSTRIP = Hh / SROWS;    // 32
constexpr int TPI = XQ * NSTRIP;      // 9728 threads per image
constexpr int BLK = 256;
constexpr int GRIDX1 = TPI / BLK;     // 38 (exact)
constexpr int NBLK1 = GRIDX1 * Bn;    // 608
constexpr int NQ4 = HW / 4;           // 107008 quad-records per image
constexpr int ITER2 = 2;
constexpr int GRIDX2 = NQ4 / (BLK * ITER2);   // 209 (exact)
constexpr int STRIDE2 = GRIDX2 * BLK;         // 53504 = NQ4/2
constexpr int NBLK2 = GRIDX2 * Bn;            // 3344

// Scratch (allocation-free: __device__ globals).
// One uint4 per 4 pixels: {pc01, pc23, tc01, tc23} packed fp16.
__device__ uint4    g_c[Bn * NQ4];
__device__ double   g_sums[Bn][3];   // [img]{sum m, sum m|pc|, sum m|tc|}
__device__ float2   g_scale[Bn];     // {Σm/Σm|pc|, Σm/Σm|tc|} per image
__device__ double   g_loss;
__device__ unsigned g_ticket1;
__device__ unsigned g_ticket2;

__device__ __forceinline__ void sort3(float& a, float& b, float& c) {
    float t;
    t = fminf(a, b); b = fmaxf(a, b); a = t;
    t = fminf(a, c); c = fmaxf(a, c); a = t;
    t = fminf(b, c); c = fmaxf(b, c); b = t;
}
__device__ __forceinline__ float med3(float a, float b, float c) {
    return fmaxf(fminf(a, b), fminf(fmaxf(a, b), c));
}
__device__ __forceinline__ float max3(float a, float b, float c) { return fmaxf(a, fmaxf(b, c)); }
__device__ __forceinline__ float min3(float a, float b, float c) { return fminf(a, fminf(b, c)); }

__device__ __forceinline__ float warp_sum(float v) {
    #pragma unroll
    for (int o = 16; o; o >>= 1) v += __shfl_down_sync(0xffffffffu, v, o);
    return v;
}

// Row load with SHUFFLE halo exchange: one predicated float4 per lane, halos come
// from neighbor lanes' registers. Strip boundaries coincide with x4 wrap, so any
// cross-strip shuffle garbage is always overwritten by the zero-pad patches.
// Only lane 0 / lane 31 mid-row do a real scalar load (2 predicated LDG per warp).
// Must be called by ALL lanes of the warp (no surrounding divergence).
__device__ __forceinline__ void load6w(const float* __restrict__ base, int yy, int x4,
                                       int lane, float v[6]) {
    bool rowok = (yy >= 0) & (yy < Hh);
    const float* p = base + yy * Ww + x4 * 4;
    float4 f = make_float4(0.f, 0.f, 0.f, 0.f);
    if (rowok) f = *reinterpret_cast<const float4*>(p);
    float left  = __shfl_up_sync(0xffffffffu, f.w, 1);
    float right = __shfl_down_sync(0xffffffffu, f.x, 1);
    if (lane == 0  && x4 > 0)      left  = rowok ? __ldg(p - 1) : 0.f;
    if (lane == 31 && x4 < XQ - 1) right = rowok ? __ldg(p + 4) : 0.f;
    if (x4 == 0)      left  = 0.f;
    if (x4 == XQ - 1) right = 0.f;
    v[0] = left; v[1] = f.x; v[2] = f.y; v[3] = f.z; v[4] = f.w; v[5] = right;
}

// 4 medians-of-9 from a 3x6 window (rows a,b,c); cs[i] = center - median9.
__device__ __forceinline__ void med4(const float a[6], const float b[6], const float c[6],
                                     float cs[4]) {
    float lo[6], mi[6], hi[6];
    #pragma unroll
    for (int i = 0; i < 6; i++) {
        float u = a[i], v = b[i], w = c[i];
        sort3(u, v, w); lo[i] = u; mi[i] = v; hi[i] = w;
    }
    #pragma unroll
    for (int i = 0; i < 4; i++) {
        float m = med3(max3(lo[i], lo[i+1], lo[i+2]),
                       med3(mi[i], mi[i+1], mi[i+2]),
                       min3(hi[i], hi[i+1], hi[i+2]));
        cs[i] = b[i + 1] - m;
    }
}

// pass1: both tensors, rolling 3-row window over an 11-row strip, shuffle halos.
// Stores interleaved fp16 contrast records; per-image sums via block reduce +
// atomics; last block computes per-image float scales (fp64 confined: 32 divides).
__global__ __launch_bounds__(BLK) void k_pass1(const float* __restrict__ pred,
                                               const float* __restrict__ targ,
                                               const float* __restrict__ mask) {
    int img = blockIdx.y;
    int t   = blockIdx.x * BLK + threadIdx.x;   // < TPI (exact)
    int lane  = threadIdx.x & 31;
    int x4    = t % XQ;
    int strip = t / XQ;
    int y0    = strip * SROWS;

    const float* pb = pred + img * HW;
    const float* tb = targ + img * HW;
    const float* mb = mask + img * HW;
    uint4* outp = g_c + img * NQ4 + x4;

    float A0[6], B0[6], C0[6], A1[6], B1[6], C1[6];
    load6w(pb, y0 - 1, x4, lane, A0);
    load6w(tb, y0 - 1, x4, lane, A1);
    load6w(pb, y0,     x4, lane, B0);
    load6w(tb, y0,     x4, lane, B1);

    float sm = 0.f, sp = 0.f, st = 0.f;
    #pragma unroll 1
    for (int r = 0; r < SROWS; r++) {
        int y = y0 + r;
        // Next-row loads (uniform calls; per-lane predication inside).
        load6w(pb, y + 1, x4, lane, C0);
        load6w(tb, y + 1, x4, lane, C1);
        float4 m4 = *reinterpret_cast<const float4*>(mb + y * Ww + x4 * 4);

        float p4[4], t4[4];
        med4(A0, B0, C0, p4);
        med4(A1, B1, C1, t4);

        sm += m4.x + m4.y + m4.z + m4.w;
        sp += m4.x * fabsf(p4[0]) + m4.y * fabsf(p4[1]) + m4.z * fabsf(p4[2]) + m4.w * fabsf(p4[3]);
        st += m4.x * fabsf(t4[0]) + m4.y * fabsf(t4[1]) + m4.z * fabsf(t4[2]) + m4.w * fabsf(t4[3]);

        __half2 h0 = __floats2half2_rn(p4[0], p4[1]);
        __half2 h1 = __floats2half2_rn(p4[2], p4[3]);
        __half2 h2 = __floats2half2_rn(t4[0], t4[1]);
        __half2 h3 = __floats2half2_rn(t4[2], t4[3]);
        uint4 rec;
        rec.x = *reinterpret_cast<unsigned*>(&h0);
        rec.y = *reinterpret_cast<unsigned*>(&h1);
        rec.z = *reinterpret_cast<unsigned*>(&h2);
        rec.w = *reinterpret_cast<unsigned*>(&h3);
        outp[y * XQ] = rec;

        #pragma unroll
        for (int i = 0; i < 6; i++) {
            A0[i] = B0[i]; B0[i] = C0[i];
            A1[i] = B1[i]; B1[i] = C1[i];
        }
    }

    __shared__ float sh[8][3];
    int w = threadIdx.x >> 5;
    sm = warp_sum(sm); sp = warp_sum(sp); st = warp_sum(st);
    if (lane == 0) { sh[w][0] = sm; sh[w][1] = sp; sh[w][2] = st; }
    __syncthreads();
    if (w == 0) {
        sm = (lane < 8) ? sh[lane][0] : 0.f;
        sp = (lane < 8) ? sh[lane][1] : 0.f;
        st = (lane < 8) ? sh[lane][2] : 0.f;
        sm = warp_sum(sm); sp = warp_sum(sp); st = warp_sum(st);
        if (lane == 0) {
            atomicAdd(&g_sums[img][0], (double)sm);
            atomicAdd(&g_sums[img][1], (double)sp);
            atomicAdd(&g_sums[img][2], (double)st);
        }
    }
    // Epilogue: last pass1 block computes per-image scales.
    if (threadIdx.x == 0) {
        __threadfence();
        unsigned tk = atomicAdd(&g_ticket1, 1u);
        if (tk == (unsigned)(NBLK1 - 1)) {
            #pragma unroll
            for (int i = 0; i < Bn; i++) {
                double d = g_sums[i][0];
                g_scale[i] = make_float2((float)(d / g_sums[i][1]),
                                         (float)(d / g_sums[i][2]));
            }
            __threadfence();
            g_ticket1 = 0u;
        }
    }
}

// pass2: one LDG.128 per 4 pixels (interleaved record), 2 records/thread.
// Last block finalizes the loss and resets state for the next graph replay.
__global__ __launch_bounds__(BLK) void k_pass2(float* __restrict__ out) {
    int img = blockIdx.y;
    int i0  = blockIdx.x * BLK + threadIdx.x;

    float2 s = g_scale[img];
    float fp = s.x, ft = s.y;

    float acc = 0.f;
    #pragma unroll
    for (int it = 0; it < ITER2; it++) {
        uint4 rec = g_c[img * NQ4 + i0 + it * STRIDE2];
        float2 p01 = __half22float2(*reinterpret_cast<__half2*>(&rec.x));
        float2 p23 = __half22float2(*reinterpret_cast<__half2*>(&rec.y));
        float2 t01 = __half22float2(*reinterpret_cast<__half2*>(&rec.z));
        float2 t23 = __half22float2(*reinterpret_cast<__half2*>(&rec.w));
        acc += fabsf(p01.x * fp - t01.x * ft) + fabsf(p01.y * fp - t01.y * ft)
             + fabsf(p23.x * fp - t23.x * ft) + fabsf(p23.y * fp - t23.y * ft);
    }

    __shared__ float sh[8];
    int lane = threadIdx.x & 31, w = threadIdx.x >> 5;
    acc = warp_sum(acc);
    if (lane == 0) sh[w] = acc;
    __syncthreads();
    if (w == 0) {
        acc = (lane < 8) ? sh[lane] : 0.f;
        acc = warp_sum(acc);
        if (lane == 0) atomicAdd(&g_loss, (double)acc);
    }
    // Last block writes the output and resets accumulators (deterministic replays).
    if (threadIdx.x == 0) {
        __threadfence();
        unsigned tk = atomicAdd(&g_ticket2, 1u);
        if (tk == (unsigned)(NBLK2 - 1)) {
            double m = 0.0, lv = atomicAdd(&g_loss, 0.0);
            #pragma unroll
            for (int i = 0; i < Bn; i++) m += g_sums[i][0];
            out[0] = (float)(lv / m);
            #pragma unroll
            for (int i = 0; i < Bn; i++) {
                g_sums[i][0] = 0.0; g_sums[i][1] = 0.0; g_sums[i][2] = 0.0;
            }
            g_loss = 0.0;
            __threadfence();
            g_ticket2 = 0u;
        }
    }
}

extern "C" void kernel_launch(void* const* d_in, const int* in_sizes, int n_in,
                              void* d_out, int out_size) {
    const float* pred = (const float*)d_in[0];
    const float* targ = (const float*)d_in[1];
    const float* mask = (const float*)d_in[2];
    float* out = (float*)d_out;

    k_pass1<<<dim3(GRIDX1, Bn), BLK>>>(pred, targ, mask);
    k_pass2<<<dim3(GRIDX2, Bn), BLK>>>(out);
}

// round 17
// speedup vs baseline: 1.0676x; 1.0676x over previous
#include <cuda_runtime.h>
#include <cuda_fp16.h>

// Problem geometry (fixed by the dataset)
constexpr int Bn = 16;
constexpr int Hh = 352;
constexpr int Ww = 1216;
constexpr int HW = Hh * Ww;           // 428032
constexpr int XQ = Ww / 4;            // 304 x4-positions per row
constexpr int SROWS = 11;             // rows per vertical strip
constexpr int NSTRIP = Hh / SROWS;    // 32
constexpr int TPI = XQ * NSTRIP;      // 9728 threads per image
constexpr int BLK = 256;
constexpr int GRIDX1 = TPI / BLK;     // 38 (exact)
constexpr int NBLK1 = GRIDX1 * Bn;    // 608
constexpr int NQ4 = HW / 4;           // 107008 quad-records per image
constexpr int ITER2 = 4;
constexpr int GRIDX2 = 4 * NQ4 / BLK; // 1672 blocks (exact; 4 images of records per pass)

// Scratch (allocation-free: __device__ globals).
// One uint4 per 4 pixels: {pc01, pc23, tc01, tc23} packed fp16.
__device__ uint4    g_c[Bn * NQ4];
__device__ double   g_sums[Bn][3];   // [img]{sum m, sum m|pc|, sum m|tc|}
__device__ float2   g_scale[Bn];     // {Σm/Σm|pc|, Σm/Σm|tc|} per image
__device__ double   g_loss;
__device__ unsigned g_ticket1;
__device__ unsigned g_ticket2;

__device__ __forceinline__ void sort3(float& a, float& b, float& c) {
    float t;
    t = fminf(a, b); b = fmaxf(a, b); a = t;
    t = fminf(a, c); c = fmaxf(a, c); a = t;
    t = fminf(b, c); c = fmaxf(b, c); b = t;
}
__device__ __forceinline__ float med3(float a, float b, float c) {
    return fmaxf(fminf(a, b), fminf(fmaxf(a, b), c));
}
__device__ __forceinline__ float max3(float a, float b, float c) { return fmaxf(a, fmaxf(b, c)); }
__device__ __forceinline__ float min3(float a, float b, float c) { return fminf(a, fminf(b, c)); }

__device__ __forceinline__ float warp_sum(float v) {
    #pragma unroll
    for (int o = 16; o; o >>= 1) v += __shfl_down_sync(0xffffffffu, v, o);
    return v;
}

__device__ __forceinline__ void zero6(float v[6]) {
    #pragma unroll
    for (int i = 0; i < 6; i++) v[i] = 0.f;
}
// Edge scalars via LDG: they alias neighbor threads' float4 sectors -> L1 hits.
// (Measured: this beats shuffle halo exchange, R16.)
__device__ __forceinline__ void load6(const float* __restrict__ row, int x4, float v[6]) {
    const float* p = row + x4 * 4;
    float4 f = *reinterpret_cast<const float4*>(p);
    v[1] = f.x; v[2] = f.y; v[3] = f.z; v[4] = f.w;
    v[0] = (x4 > 0)      ? __ldg(p - 1) : 0.f;
    v[5] = (x4 < XQ - 1) ? __ldg(p + 4) : 0.f;
}

// 4 medians-of-9 from a 3x6 window (rows a,b,c); cs[i] = center - median9.
__device__ __forceinline__ void med4(const float a[6], const float b[6], const float c[6],
                                     float cs[4]) {
    float lo[6], mi[6], hi[6];
    #pragma unroll
    for (int i = 0; i < 6; i++) {
        float u = a[i], v = b[i], w = c[i];
        sort3(u, v, w); lo[i] = u; mi[i] = v; hi[i] = w;
    }
    #pragma unroll
    for (int i = 0; i < 4; i++) {
        float m = med3(max3(lo[i], lo[i+1], lo[i+2]),
                       med3(mi[i], mi[i+1], mi[i+2]),
                       min3(hi[i], hi[i+1], hi[i+2]));
        cs[i] = b[i + 1] - m;
    }
}

// pass1: both tensors fused in one rolling-window strip loop (high MLP, one mask
// load per row). Stores interleaved fp16 contrast records; per-image sums via
// block reduce + atomics; last block computes per-image float scales.
__global__ __launch_bounds__(BLK) void k_pass1(const float* __restrict__ pred,
                                               const float* __restrict__ targ,
                                               const float* __restrict__ mask) {
    int img = blockIdx.y;
    int t   = blockIdx.x * BLK + threadIdx.x;   // < TPI (exact)
    int x4    = t % XQ;
    int strip = t / XQ;
    int y0    = strip * SROWS;

    const float* pb = pred + img * HW;
    const float* tb = targ + img * HW;
    const float* mb = mask + img * HW;
    uint4* outp = g_c + img * NQ4 + x4;

    float A0[6], B0[6], C0[6], A1[6], B1[6], C1[6];
    if (y0 > 0) {
        load6(pb + (y0 - 1) * Ww, x4, A0);
        load6(tb + (y0 - 1) * Ww, x4, A1);
    } else { zero6(A0); zero6(A1); }
    load6(pb + y0 * Ww, x4, B0);
    load6(tb + y0 * Ww, x4, B1);

    float sm = 0.f, sp = 0.f, st = 0.f;
    #pragma unroll 2
    for (int r = 0; r < SROWS; r++) {
        int y = y0 + r;
        // Next-row loads first: independent float4s + edges, overlap with compute.
        if (y + 1 < Hh) {
            load6(pb + (y + 1) * Ww, x4, C0);
            load6(tb + (y + 1) * Ww, x4, C1);
        } else { zero6(C0); zero6(C1); }
        float4 m4 = *reinterpret_cast<const float4*>(mb + y * Ww + x4 * 4);

        float p4[4], t4[4];
        med4(A0, B0, C0, p4);
        med4(A1, B1, C1, t4);

        sm += m4.x + m4.y + m4.z + m4.w;
        sp += m4.x * fabsf(p4[0]) + m4.y * fabsf(p4[1]) + m4.z * fabsf(p4[2]) + m4.w * fabsf(p4[3]);
        st += m4.x * fabsf(t4[0]) + m4.y * fabsf(t4[1]) + m4.z * fabsf(t4[2]) + m4.w * fabsf(t4[3]);

        __half2 h0 = __floats2half2_rn(p4[0], p4[1]);
        __half2 h1 = __floats2half2_rn(p4[2], p4[3]);
        __half2 h2 = __floats2half2_rn(t4[0], t4[1]);
        __half2 h3 = __floats2half2_rn(t4[2], t4[3]);
        uint4 rec;
        rec.x = *reinterpret_cast<unsigned*>(&h0);
        rec.y = *reinterpret_cast<unsigned*>(&h1);
        rec.z = *reinterpret_cast<unsigned*>(&h2);
        rec.w = *reinterpret_cast<unsigned*>(&h3);
        outp[y * XQ] = rec;

        #pragma unroll
        for (int i = 0; i < 6; i++) {
            A0[i] = B0[i]; B0[i] = C0[i];
            A1[i] = B1[i]; B1[i] = C1[i];
        }
    }

    __shared__ float sh[8][3];
    int lane = threadIdx.x & 31, w = threadIdx.x >> 5;
    sm = warp_sum(sm); sp = warp_sum(sp); st = warp_sum(st);
    if (lane == 0) { sh[w][0] = sm; sh[w][1] = sp; sh[w][2] = st; }
    __syncthreads();
    if (w == 0) {
        sm = (lane < 8) ? sh[lane][0] : 0.f;
        sp = (lane < 8) ? sh[lane][1] : 0.f;
        st = (lane < 8) ? sh[lane][2] : 0.f;
        sm = warp_sum(sm); sp = warp_sum(sp); st = warp_sum(st);
        if (lane == 0) {
            atomicAdd(&g_sums[img][0], (double)sm);
            atomicAdd(&g_sums[img][1], (double)sp);
            atomicAdd(&g_sums[img][2], (double)st);
        }
    }
    // Epilogue: last pass1 block computes per-image scales (fp64 confined: 32 divides).
    if (threadIdx.x == 0) {
        __threadfence();
        unsigned tk = atomicAdd(&g_ticket1, 1u);
        if (tk == (unsigned)(NBLK1 - 1)) {
            #pragma unroll
            for (int i = 0; i < Bn; i++) {
                double d = g_sums[i][0];
                g_scale[i] = make_float2((float)(d / g_sums[i][1]),
                                         (float)(d / g_sums[i][2]));
            }
            __threadfence();
            g_ticket1 = 0u;
        }
    }
}

// pass2: flattened 1-D grid, 4 interleaved records/thread with 4-image stride
// (img = img0 + 4*it, remainder loop-invariant -> no per-record division).
// Last block finalizes the loss and resets state for the next graph replay.
__global__ __launch_bounds__(BLK) void k_pass2(float* __restrict__ out) {
    int idx0 = blockIdx.x * BLK + threadIdx.x;  // [0, 4*NQ4)
    int img0 = idx0 / NQ4;                      // in [0, 4)
    int rem  = idx0 % NQ4;

    float acc = 0.f;
    #pragma unroll
    for (int it = 0; it < ITER2; it++) {
        int img = img0 + 4 * it;
        float2 s = g_scale[img];
        float fp = s.x, ft = s.y;
        uint4 rec = g_c[img * NQ4 + rem];
        float2 p01 = __half22float2(*reinterpret_cast<__half2*>(&rec.x));
        float2 p23 = __half22float2(*reinterpret_cast<__half2*>(&rec.y));
        float2 t01 = __half22float2(*reinterpret_cast<__half2*>(&rec.z));
        float2 t23 = __half22float2(*reinterpret_cast<__half2*>(&rec.w));
        acc += fabsf(p01.x * fp - t01.x * ft) + fabsf(p01.y * fp - t01.y * ft)
             + fabsf(p23.x * fp - t23.x * ft) + fabsf(p23.y * fp - t23.y * ft);
    }

    __shared__ float sh[8];
    int lane = threadIdx.x & 31, w = threadIdx.x >> 5;
    acc = warp_sum(acc);
    if (lane == 0) sh[w] = acc;
    __syncthreads();
    if (w == 0) {
        acc = (lane < 8) ? sh[lane] : 0.f;
        acc = warp_sum(acc);
        if (lane == 0) atomicAdd(&g_loss, (double)acc);
    }
    // Last block writes the output and resets accumulators (deterministic replays).
    if (threadIdx.x == 0) {
        __threadfence();
        unsigned tk = atomicAdd(&g_ticket2, 1u);
        if (tk == (unsigned)(GRIDX2 - 1)) {
            double m = 0.0, lv = atomicAdd(&g_loss, 0.0);
            #pragma unroll
            for (int i = 0; i < Bn; i++) m += g_sums[i][0];
            out[0] = (float)(lv / m);
            #pragma unroll
            for (int i = 0; i < Bn; i++) {
                g_sums[i][0] = 0.0; g_sums[i][1] = 0.0; g_sums[i][2] = 0.0;
            }
            g_loss = 0.0;
            __threadfence();
            g_ticket2 = 0u;
        }
    }
}

extern "C" void kernel_launch(void* const* d_in, const int* in_sizes, int n_in,
                              void* d_out, int out_size) {
    const float* pred = (const float*)d_in[0];
    const float* targ = (const float*)d_in[1];
    const float* mask = (const float*)d_in[2];
    float* out = (float*)d_out;

    k_pass1<<<dim3(GRIDX1, Bn), BLK>>>(pred, targ, mask);
    k_pass2<<<GRIDX2, BLK>>>(out);
}